// round 14
// baseline (speedup 1.0000x reference)
#include <cuda_runtime.h>
#include <cuda_fp16.h>
#include <cstdint>
#include <cfloat>

// Problem constants
#define BATCH 256
#define CW    8192
#define NC    64
#define NS    4096
#define NE    128
#define BM    128
#define BN    128            // dict entries per chunk (squarer tile)
#define NCH   (NS / BN)      // 32 chunks
#define KS    8
#define NTH   512
#define EMBED_ELEMS (BATCH * CW)
#define XSPITCH 132
#define DELTA 0.5f

// ---- smem layout (bytes) ----
#define SM_XF   0            // [8 ks][8 m16][32 lane] uint4 = 32768 (aliased by cand later)
#define SM_BF   32768        // 2 x [8 ks][8 pair][32 lane] uint4 = 65536
#define SM_XS   98304        // [128][132] fp32 = 67584
#define SM_DSQ  165888       // [2][128] float = 1024
#define SM_WIDXF 166912      // [128] int = 512
#define SM_TOTAL 167424

static __device__ __forceinline__ void mma_f16_f32(float4& c, uint32_t a0, uint32_t a1,
                                                   uint32_t a2, uint32_t a3,
                                                   uint32_t b0, uint32_t b1) {
    asm("mma.sync.aligned.m16n8k16.row.col.f32.f16.f16.f32 "
        "{%0,%1,%2,%3}, {%4,%5,%6,%7}, {%8,%9}, {%0,%1,%2,%3};"
        : "+f"(c.x), "+f"(c.y), "+f"(c.z), "+f"(c.w)
        : "r"(a0), "r"(a1), "r"(a2), "r"(a3), "r"(b0), "r"(b1));
}

static __device__ __forceinline__ uint32_t pack_h2(float f0, float f1) {
    __half2 h = __float22half2_rn(make_float2(f0, f1));
    return *(uint32_t*)&h;
}

__global__ __launch_bounds__(NTH, 1)
void vq_fused(const float* __restrict__ x, const float* __restrict__ dict,
              float* __restrict__ out) {
    extern __shared__ char smem[];
    uint4* XF = (uint4*)(smem + SM_XF);          // [ks][m16][lane]
    float* XS = (float*)(smem + SM_XS);
    float* dsq = (float*)(smem + SM_DSQ);
    int*   widxf = (int*)(smem + SM_WIDXF);
    // aliased over XF after the main loop:
    float* cand_s = (float*)(smem + SM_XF);       // [128][32]
    int*   cand_i = (int*)(smem + SM_XF + 16384); // [128][32]

    const int tid  = threadIdx.x;
    const int wid  = tid >> 5;
    const int lane = tid & 31;
    const int gid  = lane >> 2;
    const int tg   = lane & 3;
    const int mw   = wid & 3;          // 4 m-warps (32 rows each)
    const int nw2  = wid >> 2;         // 4 n-warps (32 cols each)

    const int c  = blockIdx.x;
    const int b0 = blockIdx.y * BM;

    // ---- 1. XS fill (coalesced fp32 x tile) ----
    {
        const int r = tid >> 2;
        const int q = tid & 3;
        const float* xr = x + (size_t)(b0 + r) * CW + (size_t)c * NE + q * 32;
        float* xsrow = XS + r * XSPITCH + q * 32;
        #pragma unroll
        for (int j = 0; j < 8; ++j)
            *(float4*)(xsrow + j * 4) = *(const float4*)(xr + j * 4);
    }

    // dict conversion role: thread (dn, kh) handles 32 contiguous floats (2 ks) of row dn
    const int dn = tid >> 2;               // 0..127 (dict row within chunk)
    const int kh = tid & 3;                // 0..3 (32-col half-quarter: ks = 2kh, 2kh+1)
    const float* dbase = dict + (size_t)c * NS * NE + kh * 32;

    float4 pre[8];
    {   // prefetch chunk 0 (32 floats per thread)
        const float* src = dbase + (size_t)dn * NE;
        #pragma unroll
        for (int j = 0; j < 8; ++j) pre[j] = *(const float4*)(src + j * 4);
    }
    __syncthreads();   // XS ready

    // ---- 2. XF build from XS: full A-frag (uint4) per (ks, m16, lane) ----
    #pragma unroll
    for (int e = 0; e < 4; ++e) {
        const int idx = tid + e * NTH;          // 0..2047
        const int ks  = idx >> 8;
        const int M   = (idx >> 5) & 7;
        const int ln  = idx & 31;
        const int g   = ln >> 2, t = ln & 3;
        const int r0  = M * 16 + g;
        const int kb  = ks * 16 + 2 * t;
        float2 f0 = *(const float2*)&XS[r0 * XSPITCH + kb];
        float2 f1 = *(const float2*)&XS[(r0 + 8) * XSPITCH + kb];
        float2 f2 = *(const float2*)&XS[r0 * XSPITCH + kb + 8];
        float2 f3 = *(const float2*)&XS[(r0 + 8) * XSPITCH + kb + 8];
        XF[idx] = make_uint4(pack_h2(f0.x, f0.y), pack_h2(f1.x, f1.y),
                             pack_h2(f2.x, f2.y), pack_h2(f3.x, f3.y));
    }

    // helper lambda-ish macro for converting 'pre' into a BF buffer + dsq
    const int bp_pair = dn >> 4;           // 0..7 pair
    const int bp_g    = dn & 7;
    const int bp_hf   = (dn >> 3) & 1;

#define CONVERT_PRE(BUFQ)                                                          \
    {                                                                              \
        const float* pf = (const float*)pre;                                       \
        float ss = 0.f;                                                            \
        _Pragma("unroll")                                                          \
        for (int i = 0; i < 32; ++i) ss = fmaf(pf[i], pf[i], ss);                  \
        _Pragma("unroll")                                                          \
        for (int jk = 0; jk < 2; ++jk) {                                           \
            const int ks = kh * 2 + jk;                                            \
            char* bptr = smem + SM_BF + (BUFQ) * 32768 + ks * 4096 +               \
                         bp_pair * 512 + bp_hf * 8;                                \
            _Pragma("unroll")                                                      \
            for (int t = 0; t < 4; ++t) {                                          \
                const int l0 = jk * 16 + 2 * t;                                    \
                uint2 v = make_uint2(pack_h2(pf[l0], pf[l0 + 1]),                  \
                                     pack_h2(pf[l0 + 8], pf[l0 + 9]));             \
                *(uint2*)(bptr + (bp_g * 4 + t) * 16) = v;                         \
            }                                                                      \
        }                                                                          \
        ss += __shfl_xor_sync(0xffffffffu, ss, 1);                                 \
        ss += __shfl_xor_sync(0xffffffffu, ss, 2);                                 \
        if (kh == 0) dsq[(BUFQ) * 128 + dn] = ss;                                  \
    }

    // convert chunk 0 into buffer 0
    CONVERT_PRE(0)

    // ---- per-thread state ----
    float4 acc[2][4];
    #pragma unroll
    for (int mt = 0; mt < 2; ++mt)
        #pragma unroll
        for (int nt = 0; nt < 4; ++nt) acc[mt][nt] = make_float4(0.f, 0.f, 0.f, 0.f);

    float b1[4], b2[4];
    uint32_t x12[4];                       // (x1 << 16) | x2
    #pragma unroll
    for (int i = 0; i < 4; ++i) { b1[i] = FLT_MAX; b2[i] = FLT_MAX; x12[i] = 0; }

    const int zr = tid >> 2;               // zero-fill row
    const int zj = tid & 3;
    __syncthreads();

    const int n0 = nw2 * 32;

    for (int s = 0; s < NCH; ++s) {
        const int p = s & 1;
        const char* BFp = smem + SM_BF + p * 32768;

        // ---- prefetch next chunk ----
        if (s + 1 < NCH) {
            const float* src = dbase + (size_t)((s + 1) * BN + dn) * NE;
            #pragma unroll
            for (int j = 0; j < 8; ++j) pre[j] = *(const float4*)(src + j * 4);
        }

        // ---- one-hot zero-fill: segment s (128 cols), coalesced ----
        {
            float4* dst = (float4*)(out + (size_t)EMBED_ELEMS +
                                    ((size_t)(b0 + zr) * NC + c) * NS + (size_t)s * BN);
            #pragma unroll
            for (int j = 0; j < 8; ++j)
                __stwt(&dst[zj + 4 * j], make_float4(0.f, 0.f, 0.f, 0.f));
        }

        // ---- mma phase: 8 ks x (2 A + 2 B LDS.128, 8 HMMA) ----
        #pragma unroll
        for (int ks = 0; ks < KS; ++ks) {
            uint4 A0 = XF[ks * 256 + (mw * 2) * 32 + lane];
            uint4 A1 = XF[ks * 256 + (mw * 2 + 1) * 32 + lane];
            uint4 B0 = *(const uint4*)(BFp + ks * 4096 + (nw2 * 2) * 512 + lane * 16);
            uint4 B1 = *(const uint4*)(BFp + ks * 4096 + (nw2 * 2 + 1) * 512 + lane * 16);
            mma_f16_f32(acc[0][0], A0.x, A0.y, A0.z, A0.w, B0.x, B0.y);
            mma_f16_f32(acc[0][1], A0.x, A0.y, A0.z, A0.w, B0.z, B0.w);
            mma_f16_f32(acc[0][2], A0.x, A0.y, A0.z, A0.w, B1.x, B1.y);
            mma_f16_f32(acc[0][3], A0.x, A0.y, A0.z, A0.w, B1.z, B1.w);
            mma_f16_f32(acc[1][0], A1.x, A1.y, A1.z, A1.w, B0.x, B0.y);
            mma_f16_f32(acc[1][1], A1.x, A1.y, A1.z, A1.w, B0.z, B0.w);
            mma_f16_f32(acc[1][2], A1.x, A1.y, A1.z, A1.w, B1.x, B1.y);
            mma_f16_f32(acc[1][3], A1.x, A1.y, A1.z, A1.w, B1.z, B1.w);
        }

        // ---- convert chunk s+1 into other buffer ----
        if (s + 1 < NCH) CONVERT_PRE(p ^ 1)

        // ---- epilogue: 2 groups of min-of-4 + rare top-2 insert; reset accs ----
        {
            const int baseA = s * BN + n0 + 2 * tg;
            #pragma unroll
            for (int grp = 0; grp < 2; ++grp) {           // nt pairs {0,1} and {2,3}
                const int colg = n0 + grp * 16 + 2 * tg;
                const float dA0 = dsq[p * 128 + colg];
                const float dA1 = dsq[p * 128 + colg + 1];
                const float dB0 = dsq[p * 128 + colg + 8];
                const float dB1 = dsq[p * 128 + colg + 9];
                const int base = baseA + grp * 16;
                #pragma unroll
                for (int mt = 0; mt < 2; ++mt) {
                    #pragma unroll
                    for (int h = 0; h < 2; ++h) {
                        const int sl = mt * 2 + h;
                        const float4 aA = acc[mt][grp * 2];
                        const float4 aB = acc[mt][grp * 2 + 1];
                        const float s0 = fmaf(-2.f, h ? aA.z : aA.x, dA0);
                        const float s1 = fmaf(-2.f, h ? aA.w : aA.y, dA1);
                        const float s2 = fmaf(-2.f, h ? aB.z : aB.x, dB0);
                        const float s3 = fmaf(-2.f, h ? aB.w : aB.y, dB1);
                        const float m1 = fminf(fminf(s0, s1), fminf(s2, s3));
                        if (m1 < b2[sl]) {
                            const float mn01 = fminf(s0, s1), mx01 = fmaxf(s0, s1);
                            const float mn23 = fminf(s2, s3), mx23 = fmaxf(s2, s3);
                            const float m2 = fminf(fminf(mx01, mx23), fmaxf(mn01, mn23));
                            const int p1 = (m1 == s0) ? 0 : (m1 == s1) ? 1 : (m1 == s2) ? 2 : 3;
                            const uint32_t i1 = base + (p1 & 1) + (p1 >> 1) * 8;
                            if (m1 < b1[sl]) {
                                b2[sl] = b1[sl];
                                x12[sl] = (i1 << 16) | (x12[sl] >> 16);
                                b1[sl] = m1;
                            } else {
                                b2[sl] = m1;
                                x12[sl] = (x12[sl] & 0xFFFF0000u) | i1;
                            }
                            if (m2 < b2[sl]) {
                                int p2;
                                if (m2 == s0 && p1 != 0) p2 = 0;
                                else if (m2 == s1 && p1 != 1) p2 = 1;
                                else if (m2 == s2 && p1 != 2) p2 = 2;
                                else p2 = 3;
                                b2[sl] = m2;
                                x12[sl] = (x12[sl] & 0xFFFF0000u) |
                                          (uint32_t)(base + (p2 & 1) + (p2 >> 1) * 8);
                            }
                        }
                    }
                }
            }
            #pragma unroll
            for (int mt = 0; mt < 2; ++mt)
                #pragma unroll
                for (int nt = 0; nt < 4; ++nt)
                    acc[mt][nt] = make_float4(0.f, 0.f, 0.f, 0.f);
        }
        __syncthreads();   // BF/dsq buffer handoff
    }

    // ---- stage 1: dump candidates to smem (aliases XF, safe after barrier) ----
    {
        const int slotid = nw2 * 4 + tg;
        #pragma unroll
        for (int sl = 0; sl < 4; ++sl) {
            const int R = mw * 32 + (sl >> 1) * 16 + (sl & 1) * 8 + gid;
            cand_s[R * 32 + slotid * 2]     = b1[sl];
            cand_s[R * 32 + slotid * 2 + 1] = b2[sl];
            cand_i[R * 32 + slotid * 2]     = (int)(x12[sl] >> 16);
            cand_i[R * 32 + slotid * 2 + 1] = (int)(x12[sl] & 0xFFFFu);
        }
    }
    __syncthreads();

    // ---- stage 2: warp-per-row exact rescore of near-min candidates ----
    const float* dictc = dict + (size_t)c * NS * NE;
    for (int rr = 0; rr < 8; ++rr) {
        const int r = wid * 8 + rr;
        float sc = cand_s[r * 32 + lane];
        int   ix = cand_i[r * 32 + lane];
        float m = sc;
        #pragma unroll
        for (int off = 16; off; off >>= 1)
            m = fminf(m, __shfl_xor_sync(0xffffffffu, m, off));
        float es = FLT_MAX;
        if (sc <= m + DELTA) {
            const float4* dp = (const float4*)(dictc + (size_t)ix * NE);
            const float4* xp = (const float4*)(XS + r * XSPITCH);
            float dot = 0.f, ds2 = 0.f;
            #pragma unroll 8
            for (int j = 0; j < 32; ++j) {
                const float4 d4 = __ldg(&dp[j]);
                const float4 x4 = xp[j];
                dot = fmaf(d4.x, x4.x, dot); ds2 = fmaf(d4.x, d4.x, ds2);
                dot = fmaf(d4.y, x4.y, dot); ds2 = fmaf(d4.y, d4.y, ds2);
                dot = fmaf(d4.z, x4.z, dot); ds2 = fmaf(d4.z, d4.z, ds2);
                dot = fmaf(d4.w, x4.w, dot); ds2 = fmaf(d4.w, d4.w, ds2);
            }
            es = fmaf(-2.f, dot, ds2);
        }
        #pragma unroll
        for (int off = 16; off; off >>= 1) {
            const float oe = __shfl_xor_sync(0xffffffffu, es, off);
            const int   oi = __shfl_xor_sync(0xffffffffu, ix, off);
            if (oe < es || (oe == es && oi < ix)) { es = oe; ix = oi; }
        }
        if (lane == 0) {
            out[(size_t)EMBED_ELEMS + ((size_t)(b0 + r) * NC + c) * NS + ix] = 1.0f;
            widxf[r] = ix;
        }
    }
    __syncthreads();

    // ---- stage 3: gather nearest codewords into the embed region ----
    {
        const int r = tid >> 2;
        const int q = tid & 3;
        const int ix = widxf[r];
        const float4* src = (const float4*)(dictc + (size_t)ix * NE) + q * 8;
        float4* dst = (float4*)(out + (size_t)(b0 + r) * CW + c * NE) + q * 8;
        #pragma unroll
        for (int j = 0; j < 8; ++j) __stwt(&dst[j], src[j]);
    }
}

extern "C" void kernel_launch(void* const* d_in, const int* in_sizes, int n_in,
                              void* d_out, int out_size) {
    const float* x    = (const float*)d_in[0];   // [256, 8192]
    const float* dict = (const float*)d_in[1];   // [64, 4096, 128]
    float* out = (float*)d_out;

    cudaFuncSetAttribute(vq_fused,
                         cudaFuncAttributeMaxDynamicSharedMemorySize, SM_TOTAL);

    vq_fused<<<dim3(NC, BATCH / BM), NTH, SM_TOTAL>>>(x, dict, out);
}

// round 15
// speedup vs baseline: 1.2299x; 1.2299x over previous
#include <cuda_runtime.h>
#include <cuda_fp16.h>
#include <cstdint>
#include <cfloat>

// Problem constants
#define BATCH 256
#define CW    8192
#define NC    64
#define NS    4096
#define NE    128
#define BM    128
#define BN    64
#define NCH   (NS / BN)      // 64 chunks
#define KS    8
#define NTH   512
#define EMBED_ELEMS (BATCH * CW)
#define XSPITCH 132
#define DELTA 0.5f

// ---- smem layout (bytes) ----
#define SM_BF    0            // 2 x [8 ks][4 pair][32 lane] uint4 = 32768
#define SM_XS    32768        // [128][132] fp32 = 67584
#define SM_DSQ   100352       // [2][64] float = 512
#define SM_CANDS 100864       // [128][16] float = 8192
#define SM_CANDI 109056       // [128][16] int = 8192
#define SM_WIDXF 117248       // [128] int = 512
#define SM_TOTAL 117760

static __device__ __forceinline__ void mma_f16_f32(float4& c, uint32_t a0, uint32_t a1,
                                                   uint32_t a2, uint32_t a3,
                                                   uint32_t b0, uint32_t b1) {
    asm("mma.sync.aligned.m16n8k16.row.col.f32.f16.f16.f32 "
        "{%0,%1,%2,%3}, {%4,%5,%6,%7}, {%8,%9}, {%0,%1,%2,%3};"
        : "+f"(c.x), "+f"(c.y), "+f"(c.z), "+f"(c.w)
        : "r"(a0), "r"(a1), "r"(a2), "r"(a3), "r"(b0), "r"(b1));
}

static __device__ __forceinline__ uint32_t pack_h2(float f0, float f1) {
    __half2 h = __float22half2_rn(make_float2(f0, f1));
    return *(uint32_t*)&h;
}

__global__ __launch_bounds__(NTH, 1)
void vq_fused(const float* __restrict__ x, const float* __restrict__ dict,
              float* __restrict__ out) {
    extern __shared__ char smem[];
    float* XS = (float*)(smem + SM_XS);
    float* dsq = (float*)(smem + SM_DSQ);
    float* cand_s = (float*)(smem + SM_CANDS);   // [128][16]
    int*   cand_i = (int*)(smem + SM_CANDI);     // [128][16]
    int*   widxf = (int*)(smem + SM_WIDXF);

    const int tid  = threadIdx.x;
    const int wid  = tid >> 5;
    const int lane = tid & 31;
    const int gid  = lane >> 2;
    const int tg   = lane & 3;
    const int mw   = wid & 7;          // 8 m-warps (16 rows each)
    const int nw   = wid >> 3;         // 2 n-warps (32 cols each)
    const int m0   = mw * 16;
    const int n0   = nw * 32;

    const int c  = blockIdx.x;
    const int b0 = blockIdx.y * BM;

    // ---- 1. XS fill (coalesced fp32 x tile) ----
    {
        const int r = tid >> 2;
        const int q = tid & 3;
        const float* xr = x + (size_t)(b0 + r) * CW + (size_t)c * NE + q * 32;
        float* xsrow = XS + r * XSPITCH + q * 32;
        #pragma unroll
        for (int j = 0; j < 8; ++j)
            *(float4*)(xsrow + j * 4) = *(const float4*)(xr + j * 4);
    }

    // dict conversion role: thread (dn, ksg) handles 16 contiguous floats of row dn
    const int dn  = tid >> 3;              // 0..63
    const int ksg = tid & 7;               // 0..7 == ks
    const float* dbase = dict + (size_t)c * NS * NE + ksg * 16;

    float4 pre[4];
    {   // prefetch chunk 0 (overlaps XS fill)
        const float* src = dbase + (size_t)dn * NE;
        #pragma unroll
        for (int j = 0; j < 4; ++j) pre[j] = *(const float4*)(src + j * 4);
    }
    __syncthreads();   // XS ready

    // ---- 2. A-register build: x tile fragments live in registers for ALL chunks ----
    uint4 A[KS];
    {
        const int r0 = m0 + gid;
        #pragma unroll
        for (int ks = 0; ks < KS; ++ks) {
            const int kb = ks * 16 + 2 * tg;
            float2 f0 = *(const float2*)&XS[r0 * XSPITCH + kb];
            float2 f1 = *(const float2*)&XS[(r0 + 8) * XSPITCH + kb];
            float2 f2 = *(const float2*)&XS[r0 * XSPITCH + kb + 8];
            float2 f3 = *(const float2*)&XS[(r0 + 8) * XSPITCH + kb + 8];
            A[ks] = make_uint4(pack_h2(f0.x, f0.y), pack_h2(f1.x, f1.y),
                               pack_h2(f2.x, f2.y), pack_h2(f3.x, f3.y));
        }
    }

    // BF store coords for convert role
    const int bp_pair = dn >> 4;
    const int bp_g    = dn & 7;
    const int bp_hf   = (dn >> 3) & 1;

#define CONVERT_PRE(BUFQ)                                                          \
    {                                                                              \
        const float* pf = (const float*)pre;                                       \
        float ss = 0.f;                                                            \
        _Pragma("unroll")                                                          \
        for (int i = 0; i < 16; ++i) ss = fmaf(pf[i], pf[i], ss);                  \
        char* bptr = smem + SM_BF + (BUFQ) * 16384 + ksg * 2048 +                  \
                     bp_pair * 512 + bp_hf * 8;                                    \
        _Pragma("unroll")                                                          \
        for (int t = 0; t < 4; ++t) {                                              \
            uint2 v = make_uint2(pack_h2(pf[2 * t], pf[2 * t + 1]),                \
                                 pack_h2(pf[8 + 2 * t], pf[8 + 2 * t + 1]));       \
            *(uint2*)(bptr + (bp_g * 4 + t) * 16) = v;                             \
        }                                                                          \
        ss += __shfl_xor_sync(0xffffffffu, ss, 1);                                 \
        ss += __shfl_xor_sync(0xffffffffu, ss, 2);                                 \
        ss += __shfl_xor_sync(0xffffffffu, ss, 4);                                 \
        if (ksg == 0) dsq[(BUFQ) * 64 + dn] = ss;                                  \
    }

    // convert chunk 0 into buffer 0
    CONVERT_PRE(0)

    // ---- per-thread state ----
    float4 acc[4];
    #pragma unroll
    for (int nt = 0; nt < 4; ++nt) acc[nt] = make_float4(0.f, 0.f, 0.f, 0.f);

    float b1[2], b2[2];
    uint32_t x12[2];                   // (x1 << 16) | x2
    #pragma unroll
    for (int i = 0; i < 2; ++i) { b1[i] = FLT_MAX; b2[i] = FLT_MAX; x12[i] = 0; }

    const int zr = tid >> 2;           // zero-fill row
    const int zj = tid & 3;
    __syncthreads();

    const int cb = n0 + 2 * tg;

    for (int s = 0; s < NCH; ++s) {
        const int p = s & 1;
        const char* BFp = smem + SM_BF + p * 16384;

        // ---- prefetch next chunk ----
        if (s + 1 < NCH) {
            const float* src = dbase + (size_t)((s + 1) * BN + dn) * NE;
            #pragma unroll
            for (int j = 0; j < 4; ++j) pre[j] = *(const float4*)(src + j * 4);
        }

        // ---- one-hot zero-fill: segment s, coalesced ----
        {
            float4* dst = (float4*)(out + (size_t)EMBED_ELEMS +
                                    ((size_t)(b0 + zr) * NC + c) * NS + (size_t)s * BN);
            #pragma unroll
            for (int j = 0; j < 4; ++j)
                __stwt(&dst[zj + 4 * j], make_float4(0.f, 0.f, 0.f, 0.f));
        }

        // ---- mma phase: 8 ks x (2 B LDS.128, A from registers, 4 HMMA) ----
        #pragma unroll
        for (int ks = 0; ks < KS; ++ks) {
            uint4 B0 = *(const uint4*)(BFp + ks * 2048 + (nw * 2) * 512 + lane * 16);
            uint4 B1 = *(const uint4*)(BFp + ks * 2048 + (nw * 2 + 1) * 512 + lane * 16);
            mma_f16_f32(acc[0], A[ks].x, A[ks].y, A[ks].z, A[ks].w, B0.x, B0.y);
            mma_f16_f32(acc[1], A[ks].x, A[ks].y, A[ks].z, A[ks].w, B0.z, B0.w);
            mma_f16_f32(acc[2], A[ks].x, A[ks].y, A[ks].z, A[ks].w, B1.x, B1.y);
            mma_f16_f32(acc[3], A[ks].x, A[ks].y, A[ks].z, A[ks].w, B1.z, B1.w);
        }

        // ---- convert chunk s+1 into other buffer ----
        if (s + 1 < NCH) CONVERT_PRE(p ^ 1)

        // ---- epilogue: per row-slot min-of-8 + rare top-2 insert; reset accs ----
        {
            const float2 dv0 = *(const float2*)&dsq[p * 64 + cb];
            const float2 dv1 = *(const float2*)&dsq[p * 64 + cb + 8];
            const float2 dv2 = *(const float2*)&dsq[p * 64 + cb + 16];
            const float2 dv3 = *(const float2*)&dsq[p * 64 + cb + 24];
            const int base = s * BN + cb;
            #pragma unroll
            for (int h = 0; h < 2; ++h) {      // rows gid / gid+8
                float sa[8];
                sa[0] = fmaf(-2.f, h ? acc[0].z : acc[0].x, dv0.x);
                sa[1] = fmaf(-2.f, h ? acc[0].w : acc[0].y, dv0.y);
                sa[2] = fmaf(-2.f, h ? acc[1].z : acc[1].x, dv1.x);
                sa[3] = fmaf(-2.f, h ? acc[1].w : acc[1].y, dv1.y);
                sa[4] = fmaf(-2.f, h ? acc[2].z : acc[2].x, dv2.x);
                sa[5] = fmaf(-2.f, h ? acc[2].w : acc[2].y, dv2.y);
                sa[6] = fmaf(-2.f, h ? acc[3].z : acc[3].x, dv3.x);
                sa[7] = fmaf(-2.f, h ? acc[3].w : acc[3].y, dv3.y);
                const float m1 = fminf(fminf(fminf(sa[0], sa[1]), fminf(sa[2], sa[3])),
                                       fminf(fminf(sa[4], sa[5]), fminf(sa[6], sa[7])));
                if (m1 < b2[h]) {
                    // rare path: exact top-2-of-8 with indices (ascending scan keeps first-min)
                    int p1 = 0; float mv = sa[0];
                    #pragma unroll
                    for (int i = 1; i < 8; ++i)
                        if (sa[i] < mv) { mv = sa[i]; p1 = i; }
                    const uint32_t i1 = base + (p1 >> 1) * 8 + (p1 & 1);
                    if (mv < b1[h]) {
                        b2[h] = b1[h];
                        x12[h] = (i1 << 16) | (x12[h] >> 16);
                        b1[h] = mv;
                    } else {
                        b2[h] = mv;
                        x12[h] = (x12[h] & 0xFFFF0000u) | i1;
                    }
                    sa[p1] = FLT_MAX;
                    int p2 = 0; float mv2 = sa[0];
                    #pragma unroll
                    for (int i = 1; i < 8; ++i)
                        if (sa[i] < mv2) { mv2 = sa[i]; p2 = i; }
                    if (mv2 < b2[h]) {
                        b2[h] = mv2;
                        x12[h] = (x12[h] & 0xFFFF0000u) |
                                 (uint32_t)(base + (p2 >> 1) * 8 + (p2 & 1));
                    }
                }
            }
            #pragma unroll
            for (int nt = 0; nt < 4; ++nt) acc[nt] = make_float4(0.f, 0.f, 0.f, 0.f);
        }
        __syncthreads();   // BF/dsq buffer handoff
    }

    // ---- stage 1: dump candidates (16 per row) ----
    {
        const int slotid = nw * 4 + tg;        // 0..7
        #pragma unroll
        for (int h = 0; h < 2; ++h) {
            const int R = m0 + gid + h * 8;
            cand_s[R * 16 + slotid * 2]     = b1[h];
            cand_s[R * 16 + slotid * 2 + 1] = b2[h];
            cand_i[R * 16 + slotid * 2]     = (int)(x12[h] >> 16);
            cand_i[R * 16 + slotid * 2 + 1] = (int)(x12[h] & 0xFFFFu);
        }
    }
    __syncthreads();

    // ---- stage 2: warp-per-row exact rescore of near-min candidates ----
    const float* dictc = dict + (size_t)c * NS * NE;
    for (int rr = 0; rr < 8; ++rr) {
        const int r = wid * 8 + rr;
        float sc = (lane < 16) ? cand_s[r * 16 + lane] : FLT_MAX;
        int   ix = (lane < 16) ? cand_i[r * 16 + lane] : 0;
        float m = sc;
        #pragma unroll
        for (int off = 16; off; off >>= 1)
            m = fminf(m, __shfl_xor_sync(0xffffffffu, m, off));
        float es = FLT_MAX;
        if (lane < 16 && sc <= m + DELTA) {
            const float4* dp = (const float4*)(dictc + (size_t)ix * NE);
            const float4* xp = (const float4*)(XS + r * XSPITCH);
            float dot = 0.f, ds2 = 0.f;
            #pragma unroll 8
            for (int j = 0; j < 32; ++j) {
                const float4 d4 = __ldg(&dp[j]);
                const float4 x4 = xp[j];
                dot = fmaf(d4.x, x4.x, dot); ds2 = fmaf(d4.x, d4.x, ds2);
                dot = fmaf(d4.y, x4.y, dot); ds2 = fmaf(d4.y, d4.y, ds2);
                dot = fmaf(d4.z, x4.z, dot); ds2 = fmaf(d4.z, d4.z, ds2);
                dot = fmaf(d4.w, x4.w, dot); ds2 = fmaf(d4.w, d4.w, ds2);
            }
            es = fmaf(-2.f, dot, ds2);
        }
        #pragma unroll
        for (int off = 16; off; off >>= 1) {
            const float oe = __shfl_xor_sync(0xffffffffu, es, off);
            const int   oi = __shfl_xor_sync(0xffffffffu, ix, off);
            if (oe < es || (oe == es && oi < ix)) { es = oe; ix = oi; }
        }
        if (lane == 0) {
            out[(size_t)EMBED_ELEMS + ((size_t)(b0 + r) * NC + c) * NS + ix] = 1.0f;
            widxf[r] = ix;
        }
    }
    __syncthreads();

    // ---- stage 3: gather nearest codewords into the embed region ----
    {
        const int r = tid >> 2;
        const int q = tid & 3;
        const int ix = widxf[r];
        const float4* src = (const float4*)(dictc + (size_t)ix * NE) + q * 8;
        float4* dst = (float4*)(out + (size_t)(b0 + r) * CW + c * NE) + q * 8;
        #pragma unroll
        for (int j = 0; j < 8; ++j) __stwt(&dst[j], src[j]);
    }
}

extern "C" void kernel_launch(void* const* d_in, const int* in_sizes, int n_in,
                              void* d_out, int out_size) {
    const float* x    = (const float*)d_in[0];   // [256, 8192]
    const float* dict = (const float*)d_in[1];   // [64, 4096, 128]
    float* out = (float*)d_out;

    cudaFuncSetAttribute(vq_fused,
                         cudaFuncAttributeMaxDynamicSharedMemorySize, SM_TOTAL);

    vq_fused<<<dim3(NC, BATCH / BM), NTH, SM_TOTAL>>>(x, dict, out);
}